// round 16
// baseline (speedup 1.0000x reference)
#include <cuda_runtime.h>
#include <cuda_fp16.h>
#include <cstdint>
#include <cfloat>

#define NPTS   32768
#define DDIM   64
#define KCODES 8192
#define MROWS  128
#define AROW   128                    // bytes per row (64 fp16)
#define NSTAGE 6
#define CHROWS 64
#define CHBYTES (CHROWS * AROW)       // 8192
#define NCHUNK (KCODES / CHROWS)      // 128
#define SM_A   (NSTAGE * CHBYTES)     // 49152
#define SM_EE  (SM_A + MROWS * AROW)  // 65536 (eeC ring: 256B/stage)
#define SMEM_TOTAL (SM_EE + NSTAGE * 256)   // 67072

__device__ __align__(256) __half g_A[(size_t)NPTS * DDIM];
__device__ __align__(256) __half g_B[(size_t)KCODES * DDIM];
__device__ float  g_zz[NPTS];
__device__ float  g_ee[KCODES];
__device__ float  g_eeC[KCODES];      // 65536 - 16384*ee
__device__ int    g_eemax_i;
__device__ int    g_cand[NPTS][32];
__device__ int    g_ccnt[NPTS];
__device__ int    g_idx[NPTS];
__device__ double g_loss;
__device__ int    g_done;

__device__ __forceinline__ uint32_t smem_u32(const void* p) {
    uint32_t a;
    asm("{ .reg .u64 t; cvta.to.shared.u64 t, %1; cvt.u32.u64 %0, t; }" : "=r"(a) : "l"(p));
    return a;
}
__device__ __forceinline__ void cp16(uint32_t dst, const void* src) {
    asm volatile("cp.async.cg.shared.global [%0], [%1], 16;" :: "r"(dst), "l"(src) : "memory");
}
#define CP_COMMIT() asm volatile("cp.async.commit_group;" ::: "memory")
#define CP_WAIT(n)  asm volatile("cp.async.wait_group %0;" :: "n"(n) : "memory")

#define LDMX4(r, addr) asm volatile( \
    "ldmatrix.sync.aligned.m8n8.x4.shared.b16 {%0,%1,%2,%3}, [%4];" \
    : "=r"((r)[0]), "=r"((r)[1]), "=r"((r)[2]), "=r"((r)[3]) : "r"(addr))

#define MMA(c, a, b0, b1) asm volatile( \
    "mma.sync.aligned.m16n8k16.row.col.f32.f16.f16.f32 " \
    "{%0,%1,%2,%3}, {%4,%5,%6,%7}, {%8,%9}, {%0,%1,%2,%3};" \
    : "+f"((c)[0]), "+f"((c)[1]), "+f"((c)[2]), "+f"((c)[3]) \
    : "r"((a)[0]), "r"((a)[1]), "r"((a)[2]), "r"((a)[3]), "r"(b0), "r"(b1))

// ---------------- 1) fused prep: fp16 quantize + sequential norms -------------
__global__ void vq_prep(const float* __restrict__ z, const float* __restrict__ e) {
    __shared__ float tile[64 * 65];
    const int tid = threadIdx.x;
    const bool isz = blockIdx.x < (NPTS / 256);
    const int r0 = isz ? blockIdx.x * 256 : (blockIdx.x - NPTS / 256) * 256;
    if (blockIdx.x == 0 && tid == 0) { g_loss = 0.0; g_eemax_i = 0; g_done = 0; }
    const float* src = isz ? z : e;
    const float scale = isz ? 64.f : 512.f;

    for (int it = 0; it < 4; it++) {
        const int rr = r0 + it * 64;
        __syncthreads();
        #pragma unroll
        for (int q = 0; q < 4; q++) {
            int i = tid + 256 * q;
            int row = i >> 4, c4 = i & 15;
            float4 v = ((const float4*)(src + (size_t)(rr + row) * DDIM))[c4];
            tile[row * 65 + c4 * 4 + 0] = v.x;
            tile[row * 65 + c4 * 4 + 1] = v.y;
            tile[row * 65 + c4 * 4 + 2] = v.z;
            tile[row * 65 + c4 * 4 + 3] = v.w;
            __half2 h0 = __floats2half2_rn(v.x * scale, v.y * scale);
            __half2 h1 = __floats2half2_rn(v.z * scale, v.w * scale);
            __half* dst = (isz ? g_A : g_B) + (size_t)(rr + row) * DDIM + c4 * 4;
            *(__half2*)dst = h0;
            *(__half2*)(dst + 2) = h1;
        }
        __syncthreads();
        if (tid < 64) {
            const float* p = tile + tid * 65;
            float s = 0.f;
            for (int k = 0; k < DDIM; k++) s = __fadd_rn(s, __fmul_rn(p[k], p[k]));
            int row = rr + tid;
            if (isz) {
                g_zz[row] = s;
            } else {
                g_ee[row] = s;
                g_eeC[row] = 65536.f - s * 16384.f;
                atomicMax(&g_eemax_i, __float_as_int(s));
            }
        }
    }
}

// ---------------- 2) pass 1: approx GEMM + octet-keyed top-2 ------------------
__global__ void __launch_bounds__(256, 2) vq_main() {
    extern __shared__ __align__(1024) char sm[];
    const uint32_t sbase = smem_u32(sm);
    const int tid = threadIdx.x, lane = tid & 31, wid = tid >> 5;
    const int wm = wid >> 1, wn = wid & 1;          // 4(M) x 2(N) warps
    const int row0 = blockIdx.x * MROWS;

    // A tile (one commit group)
    #pragma unroll
    for (int q = 0; q < 4; q++) {
        int i = tid + 256 * q;
        int m = i >> 3, g = i & 7;
        cp16(sbase + SM_A + m * AROW + ((g ^ (m & 7)) << 4),
             (const char*)g_A + (size_t)(row0 + m) * AROW + g * 16);
    }
    CP_COMMIT();

    auto load_chunk = [&](int c) {           // B tile + its eeC slice (one group)
        const char* src = (const char*)g_B + (size_t)c * CHROWS * AROW;
        const uint32_t st = (uint32_t)(c % NSTAGE);
        uint32_t d0 = sbase + st * CHBYTES;
        #pragma unroll
        for (int q = 0; q < 2; q++) {
            int i = tid + 256 * q;
            int n = i >> 3, g = i & 7;
            cp16(d0 + n * AROW + ((g ^ (n & 7)) << 4),
                 src + (size_t)n * AROW + g * 16);
        }
        if (tid < 16)
            cp16(sbase + SM_EE + st * 256 + tid * 16,
                 (const char*)g_eeC + (size_t)c * 256 + tid * 16);
        CP_COMMIT();
    };
    load_chunk(0); load_chunk(1); load_chunk(2); load_chunk(3);

    CP_WAIT(4);                               // A group landed
    __syncthreads();

    // A fragments -> registers, once
    uint32_t aF[4][2][4];
    {
        const uint32_t abase = sbase + SM_A + (wm * 32 + (lane & 15)) * AROW;
        #pragma unroll
        for (int kc = 0; kc < 4; kc++) {
            const int agr = kc * 2 + (lane >> 4);
            const uint32_t aoff = (uint32_t)((agr ^ (lane & 7)) << 4);
            #pragma unroll
            for (int mt = 0; mt < 2; mt++)
                LDMX4(aF[kc][mt], abase + mt * (16 * AROW) + aoff);
        }
    }

    int v1[4], v2[4];                 // octet keys: bits&~255 | chunk
    #pragma unroll
    for (int r = 0; r < 4; r++) { v1[r] = 0; v2[r] = 0; }

    const uint32_t nbase = (wn * 32 + ((lane >> 4) & 1) * 8 + (lane & 7)) * AROW;
    const int cbase = wn * 32 + 2 * (lane & 3);

    auto compute = [&](int c) {
        const uint32_t st = (uint32_t)(c % NSTAGE);
        const uint32_t bbase = sbase + st * CHBYTES + nbase;
        const float* eC = (const float*)(sm + SM_EE + st * 256);
        float2 e2[4];
        #pragma unroll
        for (int c8 = 0; c8 < 4; c8++)
            e2[c8] = *(const float2*)(eC + cbase + c8 * 8);
        float acc[2][4][4];
        #pragma unroll
        for (int mt = 0; mt < 2; mt++)
            #pragma unroll
            for (int c8 = 0; c8 < 4; c8++) {
                acc[mt][c8][0] = e2[c8].x; acc[mt][c8][1] = e2[c8].y;
                acc[mt][c8][2] = e2[c8].x; acc[mt][c8][3] = e2[c8].y;
            }
        #pragma unroll
        for (int kc = 0; kc < 4; kc++) {
            uint32_t b[2][4];
            const int bgr = kc * 2 + ((lane >> 3) & 1);
            const uint32_t boff = (uint32_t)((bgr ^ (lane & 7)) << 4);
            #pragma unroll
            for (int np = 0; np < 2; np++)
                LDMX4(b[np], bbase + np * (16 * AROW) + boff);
            #pragma unroll
            for (int mt = 0; mt < 2; mt++)
                #pragma unroll
                for (int np = 0; np < 2; np++) {
                    MMA(acc[mt][2 * np],     aF[kc][mt], b[np][0], b[np][1]);
                    MMA(acc[mt][2 * np + 1], aF[kc][mt], b[np][2], b[np][3]);
                }
        }
        // octet key per row: max over all 8 values (u>0: int order == float order)
        #pragma unroll
        for (int mt = 0; mt < 2; mt++)
            #pragma unroll
            for (int h = 0; h < 2; h++) {
                const int r = mt * 2 + h;
                int m01 = max((int)__float_as_uint(acc[mt][0][2 * h]),
                              (int)__float_as_uint(acc[mt][0][2 * h + 1]));
                int m23 = max((int)__float_as_uint(acc[mt][1][2 * h]),
                              (int)__float_as_uint(acc[mt][1][2 * h + 1]));
                int m45 = max((int)__float_as_uint(acc[mt][2][2 * h]),
                              (int)__float_as_uint(acc[mt][2][2 * h + 1]));
                int m67 = max((int)__float_as_uint(acc[mt][3][2 * h]),
                              (int)__float_as_uint(acc[mt][3][2 * h + 1]));
                int mo = max(max(m01, m23), max(m45, m67));
                int k = (int)(((uint32_t)mo & 0xFFFFFF00u) | (uint32_t)c);
                int v1r = v1[r], v2r = v2[r];
                v2r = max(v2r, min(k, v1r)); v1r = max(v1r, k);
                v1[r] = v1r; v2[r] = v2r;
            }
    };

    // Validated pipeline: loads before compute, distance 4 on 6 stages.
    for (int p = 0; p < 64; p++) {
        if (p < 63) { CP_WAIT(2); } else { CP_WAIT(0); }
        __syncthreads();
        if (p < 62) { load_chunk(2 * p + 4); load_chunk(2 * p + 5); }
        compute(2 * p);
        compute(2 * p + 1);
    }

    __syncthreads();
    int* rk = (int*)(sm + SM_A);                // [128][16] octet keys
    #pragma unroll
    for (int r = 0; r < 4; r++) {
        int row_l = wm * 32 + (r >> 1) * 16 + (r & 1) * 8 + (lane >> 2);
        int slot = wn * 8 + (lane & 3) * 2;
        rk[row_l * 16 + slot]     = v1[r];
        rk[row_l * 16 + slot + 1] = v2[r];
    }
    __syncthreads();
    if (tid < MROWS) {
        int kmax = rk[tid * 16];
        #pragma unroll
        for (int s = 1; s < 16; s++) kmax = max(kmax, rk[tid * 16 + s]);
        float vmax = __uint_as_float((uint32_t)kmax & 0xFFFFFF00u);
        float eemax = __int_as_float(g_eemax_i);
        float W = 24.0f * sqrtf(g_zz[row0 + tid] * eemax) + 18.0f;
        uint32_t thr = __float_as_uint(vmax - W);
        int cnt = 0;
        #pragma unroll
        for (int s = 0; s < 16; s++) {
            uint32_t k = (uint32_t)rk[tid * 16 + s];
            if (k >= thr && cnt <= 24) {
                int cc = k & 255;                        // chunk id
                int wn_s = s >> 3, q = (s >> 1) & 3;
                int base = cc * 64 + wn_s * 32 + q * 2;
                int* cd = g_cand[row0 + tid] + cnt;
                cd[0] = base;      cd[1] = base + 1;
                cd[2] = base + 8;  cd[3] = base + 9;
                cd[4] = base + 16; cd[5] = base + 17;
                cd[6] = base + 24; cd[7] = base + 25;
                cnt += 8;
            }
        }
        g_ccnt[row0 + tid] = cnt;
    }
}

// ---------------- 3) pass 2: exact refine, 4 candidates in parallel -----------
__global__ void vq_refine(const float* __restrict__ z, const float* __restrict__ e) {
    int row = blockIdx.x * 8 + (threadIdx.x >> 5);
    int lane = threadIdx.x & 31;
    if (row >= NPTS) return;
    const int j = lane >> 3, sub = lane & 7;
    float zf[8];
    #pragma unroll
    for (int i = 0; i < 8; i++) zf[i] = z[(size_t)row * DDIM + sub * 8 + i];
    const float zzv = g_zz[row];
    const int cnt = g_ccnt[row];
    float bd = FLT_MAX; int besti = 0x7fffffff;
    for (int t0 = 0; t0 < cnt; t0 += 4) {
        int idx = g_cand[row][t0 + j];
        const float* ep = e + (size_t)idx * DDIM + sub * 8;
        float p = 0.f;
        #pragma unroll
        for (int i = 0; i < 8; i++) p = __fmaf_rn(zf[i], ep[i], p);
        p += __shfl_xor_sync(0xffffffffu, p, 1);
        p += __shfl_xor_sync(0xffffffffu, p, 2);
        p += __shfl_xor_sync(0xffffffffu, p, 4);
        float d = __fmaf_rn(-2.f, p, __fadd_rn(zzv, g_ee[idx]));
        #pragma unroll
        for (int off = 8; off <= 16; off <<= 1) {
            float od = __shfl_xor_sync(0xffffffffu, d, off);
            int   oi = __shfl_xor_sync(0xffffffffu, idx, off);
            if (od < d || (od == d && oi < idx)) { d = od; idx = oi; }
        }
        if (d < bd || (d == bd && idx < besti)) { bd = d; besti = idx; }
    }
    if (lane == 0) g_idx[row] = besti;
}

// ---------------- 4) gather + loss (final reduce folded in) -------------------
__global__ void vq_out(const float* __restrict__ z, const float* __restrict__ emb,
                       float* __restrict__ out_zq, float* __restrict__ out_idxf,
                       float* __restrict__ out_loss) {
    int t = blockIdx.x * blockDim.x + threadIdx.x;
    int nth = gridDim.x * blockDim.x;
    double s = 0.0;
    for (int e4 = t; e4 < NPTS * DDIM / 4; e4 += nth) {
        int row = e4 >> 4;
        float4 zv = ((const float4*)z)[e4];
        float4 ev = *(const float4*)(emb + (size_t)g_idx[row] * DDIM + (e4 & 15) * 4);
        float rx = __fadd_rn(ev.x, -zv.x), ry = __fadd_rn(ev.y, -zv.y);
        float rz = __fadd_rn(ev.z, -zv.z), rw = __fadd_rn(ev.w, -zv.w);
        if (out_zq) {
            float4 o;
            o.x = __fadd_rn(zv.x, rx); o.y = __fadd_rn(zv.y, ry);
            o.z = __fadd_rn(zv.z, rz); o.w = __fadd_rn(zv.w, rw);
            ((float4*)out_zq)[e4] = o;
        }
        s += (double)__fmul_rn(rx, rx) + (double)__fmul_rn(ry, ry)
           + (double)__fmul_rn(rz, rz) + (double)__fmul_rn(rw, rw);
    }
    if (out_idxf && t < NPTS) out_idxf[t] = (float)g_idx[t];
    __shared__ double sd[256];
    sd[threadIdx.x] = s;
    __syncthreads();
    for (int o = 128; o > 0; o >>= 1) {
        if (threadIdx.x < o) sd[threadIdx.x] += sd[threadIdx.x + o];
        __syncthreads();
    }
    if (threadIdx.x == 0) {
        atomicAdd(&g_loss, sd[0]);
        __threadfence();
        int prev = atomicAdd(&g_done, 1);
        if (prev == (int)gridDim.x - 1) {
            g_done = 0;
            if (out_loss) {
                float m = (float)g_loss / (float)(NPTS * DDIM);
                out_loss[0] = __fadd_rn(__fmul_rn(0.25f, m), m);
            }
        }
    }
}

// ---------------- launch -----------------------------------------------------
extern "C" void kernel_launch(void* const* d_in, const int* in_sizes, int n_in,
                              void* d_out, int out_size) {
    const float* z   = (const float*)d_in[0];
    const float* emb = (const float*)d_in[1];
    if (n_in >= 2 && in_sizes[0] == KCODES * DDIM && in_sizes[1] == NPTS * DDIM) {
        const float* t = z; z = emb; emb = t;
    }
    float* out = (float*)d_out;
    float* out_zq = nullptr; float* out_idxf = nullptr; float* out_loss = nullptr;
    const int NZ = NPTS * DDIM;
    if (out_size >= NZ + NPTS + 1) { out_zq = out; out_idxf = out + NZ; out_loss = out + NZ + NPTS; }
    else if (out_size == NZ)   { out_zq = out; }
    else if (out_size == NPTS) { out_idxf = out; }
    else if (out_size == 1)    { out_loss = out; }
    else                       { out_zq = out; }

    cudaFuncSetAttribute(vq_main, cudaFuncAttributeMaxDynamicSharedMemorySize, SMEM_TOTAL);

    vq_prep<<<(NPTS + KCODES) / 256, 256>>>(z, emb);
    vq_main<<<NPTS / MROWS, 256, SMEM_TOTAL>>>();
    vq_refine<<<NPTS / 8, 256>>>(z, emb);
    vq_out<<<1024, 256>>>(z, emb, out_zq, out_idxf, out_loss);
}

// round 17
// speedup vs baseline: 1.0591x; 1.0591x over previous
#include <cuda_runtime.h>
#include <cuda_fp16.h>
#include <cstdint>
#include <cfloat>

#define NPTS   32768
#define DDIM   64
#define KCODES 8192
#define MROWS  128
#define AROW   128                    // bytes per row (64 fp16)
#define NSTAGE 6
#define CHROWS 64
#define CHBYTES (CHROWS * AROW)       // 8192
#define NCHUNK (KCODES / CHROWS)      // 128
#define SM_A   (NSTAGE * CHBYTES)     // 49152
#define SM_EE  (SM_A + MROWS * AROW)  // 65536
#define SMEM_TOTAL (SM_EE + KCODES * 4)   // 98304

__device__ __align__(256) __half g_A[(size_t)NPTS * DDIM];
__device__ __align__(256) __half g_B[(size_t)KCODES * DDIM];
__device__ float  g_zz[NPTS];
__device__ float  g_ee[KCODES];
__device__ float  g_eeC[KCODES];      // 65536 - 16384*ee
__device__ int    g_eemax_i;
__device__ int    g_cand[NPTS][32];
__device__ int    g_ccnt[NPTS];
__device__ double g_loss;

__device__ __forceinline__ uint32_t smem_u32(const void* p) {
    uint32_t a;
    asm("{ .reg .u64 t; cvta.to.shared.u64 t, %1; cvt.u32.u64 %0, t; }" : "=r"(a) : "l"(p));
    return a;
}
__device__ __forceinline__ void cp16(uint32_t dst, const void* src) {
    asm volatile("cp.async.cg.shared.global [%0], [%1], 16;" :: "r"(dst), "l"(src) : "memory");
}
#define CP_COMMIT() asm volatile("cp.async.commit_group;" ::: "memory")
#define CP_WAIT(n)  asm volatile("cp.async.wait_group %0;" :: "n"(n) : "memory")

#define LDMX4(r, addr) asm volatile( \
    "ldmatrix.sync.aligned.m8n8.x4.shared.b16 {%0,%1,%2,%3}, [%4];" \
    : "=r"((r)[0]), "=r"((r)[1]), "=r"((r)[2]), "=r"((r)[3]) : "r"(addr))

#define MMA(c, a, b0, b1) asm volatile( \
    "mma.sync.aligned.m16n8k16.row.col.f32.f16.f16.f32 " \
    "{%0,%1,%2,%3}, {%4,%5,%6,%7}, {%8,%9}, {%0,%1,%2,%3};" \
    : "+f"((c)[0]), "+f"((c)[1]), "+f"((c)[2]), "+f"((c)[3]) \
    : "r"((a)[0]), "r"((a)[1]), "r"((a)[2]), "r"((a)[3]), "r"(b0), "r"(b1))

// ---------------- 1) fused prep: fp16 quantize + sequential norms -------------
__global__ void vq_prep(const float* __restrict__ z, const float* __restrict__ e) {
    __shared__ float tile[64 * 65];
    const int tid = threadIdx.x;
    const bool isz = blockIdx.x < (NPTS / 256);
    const int r0 = isz ? blockIdx.x * 256 : (blockIdx.x - NPTS / 256) * 256;
    if (blockIdx.x == 0 && tid == 0) { g_loss = 0.0; g_eemax_i = 0; }
    const float* src = isz ? z : e;
    const float scale = isz ? 64.f : 512.f;

    for (int it = 0; it < 4; it++) {
        const int rr = r0 + it * 64;
        __syncthreads();
        #pragma unroll
        for (int q = 0; q < 4; q++) {
            int i = tid + 256 * q;
            int row = i >> 4, c4 = i & 15;
            float4 v = ((const float4*)(src + (size_t)(rr + row) * DDIM))[c4];
            tile[row * 65 + c4 * 4 + 0] = v.x;
            tile[row * 65 + c4 * 4 + 1] = v.y;
            tile[row * 65 + c4 * 4 + 2] = v.z;
            tile[row * 65 + c4 * 4 + 3] = v.w;
            __half2 h0 = __floats2half2_rn(v.x * scale, v.y * scale);
            __half2 h1 = __floats2half2_rn(v.z * scale, v.w * scale);
            __half* dst = (isz ? g_A : g_B) + (size_t)(rr + row) * DDIM + c4 * 4;
            *(__half2*)dst = h0;
            *(__half2*)(dst + 2) = h1;
        }
        __syncthreads();
        if (tid < 64) {
            const float* p = tile + tid * 65;
            float s = 0.f;
            for (int k = 0; k < DDIM; k++) s = __fadd_rn(s, __fmul_rn(p[k], p[k]));
            int row = rr + tid;
            if (isz) {
                g_zz[row] = s;
            } else {
                g_ee[row] = s;
                g_eeC[row] = 65536.f - s * 16384.f;
                atomicMax(&g_eemax_i, __float_as_int(s));
            }
        }
    }
}

// ---------------- 2) pass 1: approx GEMM + quad-keyed top-2 (R14 exact) -------
__global__ void __launch_bounds__(256, 2) vq_main() {
    extern __shared__ __align__(1024) char sm[];
    const uint32_t sbase = smem_u32(sm);
    const int tid = threadIdx.x, lane = tid & 31, wid = tid >> 5;
    const int wm = wid >> 1, wn = wid & 1;          // 4(M) x 2(N) warps
    const int row0 = blockIdx.x * MROWS;

    #pragma unroll
    for (int q = 0; q < 4; q++) {
        int i = tid + 256 * q;
        int m = i >> 3, g = i & 7;
        cp16(sbase + SM_A + m * AROW + ((g ^ (m & 7)) << 4),
             (const char*)g_A + (size_t)(row0 + m) * AROW + g * 16);
    }
    #pragma unroll
    for (int q = 0; q < 8; q++) {
        int i = tid + 256 * q;
        cp16(sbase + SM_EE + i * 16, (const char*)g_eeC + i * 16);
    }
    CP_COMMIT();

    auto load_chunk = [&](int c) {
        const char* src = (const char*)g_B + (size_t)c * CHROWS * AROW;
        uint32_t d0 = sbase + (uint32_t)(c % NSTAGE) * CHBYTES;
        #pragma unroll
        for (int q = 0; q < 2; q++) {
            int i = tid + 256 * q;
            int n = i >> 3, g = i & 7;
            cp16(d0 + n * AROW + ((g ^ (n & 7)) << 4),
                 src + (size_t)n * AROW + g * 16);
        }
        CP_COMMIT();
    };
    load_chunk(0); load_chunk(1); load_chunk(2); load_chunk(3);

    CP_WAIT(4);
    __syncthreads();

    uint32_t aF[4][2][4];
    {
        const uint32_t abase = sbase + SM_A + (wm * 32 + (lane & 15)) * AROW;
        #pragma unroll
        for (int kc = 0; kc < 4; kc++) {
            const int agr = kc * 2 + (lane >> 4);
            const uint32_t aoff = (uint32_t)((agr ^ (lane & 7)) << 4);
            #pragma unroll
            for (int mt = 0; mt < 2; mt++)
                LDMX4(aF[kc][mt], abase + mt * (16 * AROW) + aoff);
        }
    }

    int v1[4], v2[4];                 // packed quad keys: bits&~255 | code
    #pragma unroll
    for (int r = 0; r < 4; r++) { v1[r] = 0; v2[r] = 0; }

    const uint32_t nbase = (wn * 32 + ((lane >> 4) & 1) * 8 + (lane & 7)) * AROW;
    const int cbase = wn * 32 + 2 * (lane & 3);

    auto compute = [&](int c) {
        const uint32_t bbase = sbase + (uint32_t)(c % NSTAGE) * CHBYTES + nbase;
        float2 e2[4];
        #pragma unroll
        for (int c8 = 0; c8 < 4; c8++)
            e2[c8] = *(const float2*)(sm + SM_EE + (c * 64 + cbase + c8 * 8) * 4);
        float acc[2][4][4];
        #pragma unroll
        for (int mt = 0; mt < 2; mt++)
            #pragma unroll
            for (int c8 = 0; c8 < 4; c8++) {
                acc[mt][c8][0] = e2[c8].x; acc[mt][c8][1] = e2[c8].y;
                acc[mt][c8][2] = e2[c8].x; acc[mt][c8][3] = e2[c8].y;
            }
        #pragma unroll
        for (int kc = 0; kc < 4; kc++) {
            uint32_t b[2][4];
            const int bgr = kc * 2 + ((lane >> 3) & 1);
            const uint32_t boff = (uint32_t)((bgr ^ (lane & 7)) << 4);
            #pragma unroll
            for (int np = 0; np < 2; np++)
                LDMX4(b[np], bbase + np * (16 * AROW) + boff);
            #pragma unroll
            for (int mt = 0; mt < 2; mt++)
                #pragma unroll
                for (int np = 0; np < 2; np++) {
                    MMA(acc[mt][2 * np],     aF[kc][mt], b[np][0], b[np][1]);
                    MMA(acc[mt][2 * np + 1], aF[kc][mt], b[np][2], b[np][3]);
                }
        }
        const int code0 = c * 2;
        #pragma unroll
        for (int mt = 0; mt < 2; mt++)
            #pragma unroll
            for (int h = 0; h < 2; h++) {
                const int r = mt * 2 + h;
                int q0 = max(max((int)__float_as_uint(acc[mt][0][2 * h]),
                                 (int)__float_as_uint(acc[mt][0][2 * h + 1])),
                             max((int)__float_as_uint(acc[mt][1][2 * h]),
                                 (int)__float_as_uint(acc[mt][1][2 * h + 1])));
                int q1 = max(max((int)__float_as_uint(acc[mt][2][2 * h]),
                                 (int)__float_as_uint(acc[mt][2][2 * h + 1])),
                             max((int)__float_as_uint(acc[mt][3][2 * h]),
                                 (int)__float_as_uint(acc[mt][3][2 * h + 1])));
                int k0 = (int)(((uint32_t)q0 & 0xFFFFFF00u) | (uint32_t)code0);
                int k1 = (int)(((uint32_t)q1 & 0xFFFFFF00u) | (uint32_t)(code0 + 1));
                int v1r = v1[r], v2r = v2[r];
                v2r = max(v2r, min(k0, v1r)); v1r = max(v1r, k0);
                v2r = max(v2r, min(k1, v1r)); v1r = max(v1r, k1);
                v1[r] = v1r; v2[r] = v2r;
            }
    };

    for (int p = 0; p < 64; p++) {
        if (p < 63) { CP_WAIT(2); } else { CP_WAIT(0); }
        __syncthreads();
        if (p < 62) { load_chunk(2 * p + 4); load_chunk(2 * p + 5); }
        compute(2 * p);
        compute(2 * p + 1);
    }

    __syncthreads();
    int* rk = (int*)(sm + SM_A);                // [128][16] packed quad keys
    #pragma unroll
    for (int r = 0; r < 4; r++) {
        int row_l = wm * 32 + (r >> 1) * 16 + (r & 1) * 8 + (lane >> 2);
        int slot = wn * 8 + (lane & 3) * 2;
        rk[row_l * 16 + slot]     = v1[r];
        rk[row_l * 16 + slot + 1] = v2[r];
    }
    __syncthreads();
    if (tid < MROWS) {
        int kmax = rk[tid * 16];
        #pragma unroll
        for (int s = 1; s < 16; s++) kmax = max(kmax, rk[tid * 16 + s]);
        float vmax = __uint_as_float((uint32_t)kmax & 0xFFFFFF00u);
        float eemax = __int_as_float(g_eemax_i);
        float W = 24.0f * sqrtf(g_zz[row0 + tid] * eemax) + 18.0f;
        uint32_t thr = __float_as_uint(vmax - W);
        int cnt = 0;
        #pragma unroll
        for (int s = 0; s < 16; s++) {
            uint32_t k = (uint32_t)rk[tid * 16 + s];
            if (k >= thr && cnt <= 28) {
                int code = k & 255;
                int cc = code >> 1, qh = code & 1;
                int wn_s = s >> 3, q = (s >> 1) & 3;
                int base = cc * 64 + wn_s * 32 + q * 2 + qh * 16;
                g_cand[row0 + tid][cnt]     = base;
                g_cand[row0 + tid][cnt + 1] = base + 1;
                g_cand[row0 + tid][cnt + 2] = base + 8;
                g_cand[row0 + tid][cnt + 3] = base + 9;
                cnt += 4;
            }
        }
        g_ccnt[row0 + tid] = cnt;
    }
}

// ---------------- 3) fused finish: exact refine + gather + zq + loss ----------
// One warp per row. After the cross-octet reduce, every lane holds (bd,besti),
// so the same warp gathers e[besti], writes zq/idx, and accumulates the loss.
__global__ void vq_finish(const float* __restrict__ z, const float* __restrict__ e,
                          float* __restrict__ out_zq, float* __restrict__ out_idxf) {
    const int row = blockIdx.x * 8 + (threadIdx.x >> 5);
    const int lane = threadIdx.x & 31;
    const int j = lane >> 3, sub = lane & 7;
    float zf[8];
    #pragma unroll
    for (int i = 0; i < 8; i++) zf[i] = z[(size_t)row * DDIM + sub * 8 + i];
    const float zzv = g_zz[row];
    const int cnt = g_ccnt[row];
    float bd = FLT_MAX; int besti = 0x7fffffff;
    for (int t0 = 0; t0 < cnt; t0 += 4) {
        int idx = g_cand[row][t0 + j];
        const float* ep = e + (size_t)idx * DDIM + sub * 8;
        float p = 0.f;
        #pragma unroll
        for (int i = 0; i < 8; i++) p = __fmaf_rn(zf[i], ep[i], p);
        p += __shfl_xor_sync(0xffffffffu, p, 1);
        p += __shfl_xor_sync(0xffffffffu, p, 2);
        p += __shfl_xor_sync(0xffffffffu, p, 4);
        float d = __fmaf_rn(-2.f, p, __fadd_rn(zzv, g_ee[idx]));
        #pragma unroll
        for (int off = 8; off <= 16; off <<= 1) {
            float od = __shfl_xor_sync(0xffffffffu, d, off);
            int   oi = __shfl_xor_sync(0xffffffffu, idx, off);
            if (od < d || (od == d && oi < idx)) { d = od; idx = oi; }
        }
        if (d < bd || (d == bd && idx < besti)) { bd = d; besti = idx; }
    }
    // ---- output: zq = fl(z + fl(e-z)), idx, loss (same rounding as before) ----
    float zv0 = z[(size_t)row * DDIM + lane];
    float zv1 = z[(size_t)row * DDIM + 32 + lane];
    const float* ep = e + (size_t)besti * DDIM;
    float r0 = __fadd_rn(ep[lane], -zv0);
    float r1 = __fadd_rn(ep[32 + lane], -zv1);
    if (out_zq) {
        out_zq[(size_t)row * DDIM + lane]      = __fadd_rn(zv0, r0);
        out_zq[(size_t)row * DDIM + 32 + lane] = __fadd_rn(zv1, r1);
    }
    if (out_idxf && lane == 0) out_idxf[row] = (float)besti;
    double s = (double)__fmul_rn(r0, r0) + (double)__fmul_rn(r1, r1);
    #pragma unroll
    for (int off = 16; off; off >>= 1)
        s += __shfl_xor_sync(0xffffffffu, s, off);
    __shared__ double sd[8];
    if (lane == 0) sd[threadIdx.x >> 5] = s;
    __syncthreads();
    if (threadIdx.x == 0) {
        double t = 0.0;
        #pragma unroll
        for (int w = 0; w < 8; w++) t += sd[w];
        atomicAdd(&g_loss, t);
    }
}

__global__ void vq_loss(float* __restrict__ out_loss) {
    float m = (float)g_loss / (float)(NPTS * DDIM);
    out_loss[0] = __fadd_rn(__fmul_rn(0.25f, m), m);
}

// ---------------- launch -----------------------------------------------------
extern "C" void kernel_launch(void* const* d_in, const int* in_sizes, int n_in,
                              void* d_out, int out_size) {
    const float* z   = (const float*)d_in[0];
    const float* emb = (const float*)d_in[1];
    if (n_in >= 2 && in_sizes[0] == KCODES * DDIM && in_sizes[1] == NPTS * DDIM) {
        const float* t = z; z = emb; emb = t;
    }
    float* out = (float*)d_out;
    float* out_zq = nullptr; float* out_idxf = nullptr; float* out_loss = nullptr;
    const int NZ = NPTS * DDIM;
    if (out_size >= NZ + NPTS + 1) { out_zq = out; out_idxf = out + NZ; out_loss = out + NZ + NPTS; }
    else if (out_size == NZ)   { out_zq = out; }
    else if (out_size == NPTS) { out_idxf = out; }
    else if (out_size == 1)    { out_loss = out; }
    else                       { out_zq = out; }

    cudaFuncSetAttribute(vq_main, cudaFuncAttributeMaxDynamicSharedMemorySize, SMEM_TOTAL);

    vq_prep<<<(NPTS + KCODES) / 256, 256>>>(z, emb);
    vq_main<<<NPTS / MROWS, 256, SMEM_TOTAL>>>();
    vq_finish<<<NPTS / 8, 256>>>(z, emb, out_zq, out_idxf);
    if (out_loss) vq_loss<<<1, 1>>>(out_loss);
}